// round 15
// baseline (speedup 1.0000x reference)
#include <cuda_runtime.h>
#include <cstdint>
#include <mma.h>

using namespace nvcuda;

// ---------------------------------------------------------------------------
// Shapes
// ---------------------------------------------------------------------------
namespace {
constexpr int BN   = 64;
constexpr int HWIN = 240;
constexpr int H1   = 120;
constexpr int H2   = 60;
constexpr int C0   = 3;
constexpr int C1   = 32;
constexpr int C2   = 64;
constexpr int C3   = 128;
constexpr int HEADN = 1280;
constexpr int PIX2  = H2 * H2;                 // 3600
constexpr int NTAP = 9;

// conv1 WMMA geometry
constexpr int C1A_LD = 36;                     // A [128][36]
constexpr int C1B_LD = 36;                     // B [32][36]
constexpr int C1RAW  = 244;                    // raw row: ix -1..242 (padded)

// conv2 SMEM plan (floats) — double-buffered A + per-tap B slices (R14)
constexpr int SA_LD   = 36;
constexpr int SB_LD   = 68;
constexpr int SA_SZ   = 128 * SA_LD;           // 4608
constexpr int SB_SZ   = 32 * SB_LD;            // 2176
constexpr int S2_A0   = 0;
constexpr int S2_A1   = SA_SZ;
constexpr int S2_B0   = 2 * SA_SZ;
constexpr int S2_B1   = 2 * SA_SZ + SB_SZ;
constexpr int S2_FLTS = 2 * SA_SZ + 2 * SB_SZ; // 13568 floats
constexpr int SOUT_LD = 132;
constexpr int S2_TOTAL = S2_FLTS * 4;          // 54272 B

// conv3 geometry (R10/R14 proven config)
constexpr int P3     = 128;
constexpr int NCHUNK = (PIX2 + P3 - 1) / P3;   // 29
constexpr int SW_LD  = 68;
constexpr int SH_LD  = 132;
constexpr int S3_OUT_LD = 68;
constexpr int S3_TOTAL  = (8704 + 8704) * 4;   // 69632 B
}

// ---------------------------------------------------------------------------
// Scratch
// ---------------------------------------------------------------------------
__device__ float g_h1[(size_t)BN * H1 * H1 * C1];   // channels-last
__device__ float g_h2[(size_t)BN * C2 * PIX2];      // channel-major
__device__ float g_part[BN * NCHUNK * C3];
__device__ float g_w1b[32 * C1];                    // conv1 B [k(32)][co], tf32, a-folded
__device__ float g_w2b[288 * C2];                   // conv2 B [tap*32+ci][co], tf32
__device__ float g_w2a[C3 * C2];                    // conv3 A [co3][k], tf32, a2-folded

__device__ __forceinline__ float f2tf(float x) {
    uint32_t r;
    asm("cvt.rna.tf32.f32 %0, %1;" : "=r"(r) : "f"(x));
    return __uint_as_float(r);
}

// ---------------------------------------------------------------------------
// Prep: conv1 B (a_stem-folded, tf32, K padded to 32), conv2 B, conv3 A
// ---------------------------------------------------------------------------
__global__ void prep_kernel(const float* __restrict__ wstem,
                            const float* __restrict__ astem,
                            const float* __restrict__ w1,
                            const float* __restrict__ a1,
                            const float* __restrict__ w2,
                            const float* __restrict__ a2) {
    int i = blockIdx.x * blockDim.x + threadIdx.x;
    if (i < 32 * C1) {                 // conv1 B: k = ci*9+ky*3+kx, rows 27..31 zero
        int k = i >> 5, co = i & 31;
        g_w1b[k * C1 + co] = (k < 27) ? f2tf(wstem[co * 27 + k] * astem[co]) : 0.f;
    }
    if (i < C3 * C2) {
        g_w2a[i] = f2tf(w2[i] * a2[i >> 6]);
    }
    if (i < C2 * 288) {
        int co = i / 288, r = i % 288;
        int ci = r / 9, tap = r % 9;
        g_w2b[(tap * 32 + ci) * C2 + co] = f2tf(w1[i] * a1[co]);
    }
}

// ---------------------------------------------------------------------------
// Conv1: WMMA tf32 implicit GEMM. 3->32, 3x3 s2 p1, 240^2 -> 120^2.
// CTA = 1 output row: M=128 px (120 valid), N=32 co, K=32 (27 + pad).
// Raw x rows staged coalesced; A built from smem; epilogue channels-last.
// ---------------------------------------------------------------------------
__global__ __launch_bounds__(256) void conv1_mma_kernel(
        const float* __restrict__ x,
        const float* __restrict__ bstem) {
    __shared__ float raw[9][C1RAW];       // [ci*3+ky][ix+1]
    __shared__ float sB[32][C1B_LD];
    __shared__ float sA[128][C1A_LD];     // mainloop A; epilogue overlay
    __shared__ float bs[C1];

    int oy = blockIdx.x, n = blockIdx.y;
    int tx = threadIdx.x;
    int wid = tx >> 5;

    if (tx < C1) bs[tx] = bstem[tx];

    // stage B (pre-rounded tf32, pre-padded): 32 rows x 8 float4
    for (int i = tx; i < 32 * 8; i += 256) {
        int r = i >> 3, c4 = i & 7;
        *(float4*)&sB[r][c4 * 4] = *(const float4*)&g_w1b[r * C1 + c4 * 4];
    }

    // stage raw x rows (coalesced)
    const float* xn = x + (size_t)n * C0 * HWIN * HWIN;
    for (int i = tx; i < 9 * C1RAW; i += 256) {
        int r = i / C1RAW, j = i % C1RAW;
        int ci = r / 3, ky = r % 3;
        int iy = oy * 2 - 1 + ky;
        int ix = j - 1;
        float v = 0.f;
        if ((unsigned)iy < (unsigned)HWIN && (unsigned)ix < (unsigned)HWIN)
            v = xn[(size_t)ci * HWIN * HWIN + iy * HWIN + ix];
        raw[r][j] = v;
    }
    __syncthreads();

    // build A [128 px][32 k]: k = ci*9 + ky*3 + kx ; ix+1 = 2*px + kx
    for (int i = tx; i < 128 * 32; i += 256) {
        int px = i >> 5, k = i & 31;
        float v = 0.f;
        if (k < 27 && px < 120) {
            int ci = k / 9, r = k % 9;
            int ky = r / 3, kx = r % 3;
            v = raw[ci * 3 + ky][2 * px + kx];
        }
        sA[px][k] = f2tf(v);
    }
    __syncthreads();

    // GEMM: 8 warps = 4 px-groups x 2 co-groups; warp tile 32px x 16co
    int wm = wid & 3, wn = wid >> 2;

    wmma::fragment<wmma::accumulator, 16, 16, 8, float> c[2];
#pragma unroll
    for (int i = 0; i < 2; i++) wmma::fill_fragment(c[i], 0.f);

#pragma unroll
    for (int s = 0; s < 4; s++) {
        wmma::fragment<wmma::matrix_a, 16, 16, 8, wmma::precision::tf32,
                       wmma::row_major> a[2];
        wmma::fragment<wmma::matrix_b, 16, 16, 8, wmma::precision::tf32,
                       wmma::row_major> b;
#pragma unroll
        for (int i = 0; i < 2; i++)
            wmma::load_matrix_sync(a[i], &sA[wm * 32 + i * 16][s * 8], C1A_LD);
        wmma::load_matrix_sync(b, &sB[s * 8][wn * 16], C1B_LD);
#pragma unroll
        for (int i = 0; i < 2; i++)
            wmma::mma_sync(c[i], a[i], b, c[i]);
    }
    __syncthreads();                      // sA reads done; overlay as sOut

    float (*sOut)[C1A_LD] = sA;           // [128][36] row-major [px][co]
#pragma unroll
    for (int i = 0; i < 2; i++)
        wmma::store_matrix_sync(&sOut[wm * 32 + i * 16][wn * 16],
                                c[i], C1A_LD, wmma::mem_row_major);
    __syncthreads();

    // epilogue: +bias, ReLU, channels-last float4 stores
    {
        int px = tx >> 1, half = (tx & 1) * 16;
        if (px < 120) {
            float* o = g_h1 + (((size_t)n * H1 + oy) * H1 + px) * C1 + half;
            const float* src = &sOut[px][half];
#pragma unroll
            for (int q = 0; q < 4; q++) {
                float4 y;
                y.x = fmaxf(src[q * 4 + 0] + bs[half + q * 4 + 0], 0.f);
                y.y = fmaxf(src[q * 4 + 1] + bs[half + q * 4 + 1], 0.f);
                y.z = fmaxf(src[q * 4 + 2] + bs[half + q * 4 + 2], 0.f);
                y.w = fmaxf(src[q * 4 + 3] + bs[half + q * 4 + 3], 0.f);
                *(float4*)&o[q * 4] = y;
            }
        }
    }
}

// ---------------------------------------------------------------------------
// Conv2: WMMA tf32 implicit GEMM, double-buffered (exact R14 form).
// ---------------------------------------------------------------------------
__global__ __launch_bounds__(256) void conv2_mma_kernel(
        const float* __restrict__ b1) {
    extern __shared__ float smf[];
    float* sAb[2] = { smf + S2_A0, smf + S2_A1 };
    float* sBb[2] = { smf + S2_B0, smf + S2_B1 };
    __shared__ float bs[C2];

    int tx = threadIdx.x;
    int wid = tx >> 5;
    int oy0 = blockIdx.x * 2;
    int n = blockIdx.y;

    if (tx < C2) bs[tx] = b1[tx];

    int wm = wid & 3;
    int wn = wid >> 2;

    wmma::fragment<wmma::accumulator, 16, 16, 8, float> c[2][2];
#pragma unroll
    for (int i = 0; i < 2; i++)
#pragma unroll
        for (int j = 0; j < 2; j++) wmma::fill_fragment(c[i][j], 0.f);

    const float* h1n = g_h1 + (size_t)n * H1 * H1 * C1;

    int ipx[4], ic4[4], ioy[4], iox[4];
    bool ival[4];
#pragma unroll
    for (int it = 0; it < 4; it++) {
        int i = tx + it * 256;
        ipx[it] = i >> 3;
        ic4[it] = i & 7;
        ival[it] = (ipx[it] < 120);
        ioy[it] = oy0 + (ipx[it] >= 60 ? 1 : 0);
        iox[it] = ipx[it] >= 60 ? ipx[it] - 60 : ipx[it];
    }
    int brow[2], bc4[2];
#pragma unroll
    for (int it = 0; it < 2; it++) {
        int i = tx + it * 256;
        brow[it] = i >> 4;
        bc4[it]  = i & 15;
    }

    auto ldA = [&](int tap, int it) -> float4 {
        int ky = tap / 3, kx = tap % 3;
        float4 v = make_float4(0.f, 0.f, 0.f, 0.f);
        if (ival[it]) {
            int iy = ioy[it] * 2 - 1 + ky;
            int ix = iox[it] * 2 - 1 + kx;
            if ((unsigned)iy < (unsigned)H1 && (unsigned)ix < (unsigned)H1)
                v = *(const float4*)&h1n[((size_t)iy * H1 + ix) * C1 + ic4[it] * 4];
        }
        return v;
    };
    auto ldB = [&](int tap, int it) -> float4 {
        return *(const float4*)&g_w2b[(tap * 32 + brow[it]) * C2 + bc4[it] * 4];
    };
    auto stA = [&](float4* v, float* dst) {
#pragma unroll
        for (int it = 0; it < 4; it++) {
            float4 t;
            t.x = f2tf(v[it].x); t.y = f2tf(v[it].y);
            t.z = f2tf(v[it].z); t.w = f2tf(v[it].w);
            *(float4*)&dst[ipx[it] * SA_LD + ic4[it] * 4] = t;
        }
    };
    auto stB = [&](float4* v, float* dst) {
#pragma unroll
        for (int it = 0; it < 2; it++)
            *(float4*)&dst[brow[it] * SB_LD + bc4[it] * 4] = v[it];
    };

    {
        float4 v[4], vb[2];
#pragma unroll
        for (int it = 0; it < 4; it++) v[it] = ldA(0, it);
#pragma unroll
        for (int it = 0; it < 2; it++) vb[it] = ldB(0, it);
        stA(v, sAb[0]);
        stB(vb, sBb[0]);
    }
    __syncthreads();

    for (int tap = 0; tap < NTAP; tap++) {
        int cur = tap & 1, nxt = cur ^ 1;

        float4 vn[4], vbn[2];
        if (tap < NTAP - 1) {
#pragma unroll
            for (int it = 0; it < 4; it++) vn[it] = ldA(tap + 1, it);
#pragma unroll
            for (int it = 0; it < 2; it++) vbn[it] = ldB(tap + 1, it);
        }

        float* sA = sAb[cur];
        float* sB = sBb[cur];
#pragma unroll
        for (int s = 0; s < 4; s++) {
            wmma::fragment<wmma::matrix_a, 16, 16, 8, wmma::precision::tf32,
                           wmma::row_major> a[2];
            wmma::fragment<wmma::matrix_b, 16, 16, 8, wmma::precision::tf32,
                           wmma::row_major> b[2];
#pragma unroll
            for (int i = 0; i < 2; i++)
                wmma::load_matrix_sync(a[i],
                    &sA[(wm * 32 + i * 16) * SA_LD + s * 8], SA_LD);
#pragma unroll
            for (int j = 0; j < 2; j++)
                wmma::load_matrix_sync(b[j],
                    &sB[(s * 8) * SB_LD + wn * 32 + j * 16], SB_LD);
#pragma unroll
            for (int i = 0; i < 2; i++)
#pragma unroll
                for (int j = 0; j < 2; j++)
                    wmma::mma_sync(c[i][j], a[i], b[j], c[i][j]);
        }

        if (tap < NTAP - 1) {
            stA(vn, sAb[nxt]);
            stB(vbn, sBb[nxt]);
        }
        __syncthreads();
    }

    float* sOut = smf;
#pragma unroll
    for (int i = 0; i < 2; i++)
#pragma unroll
        for (int j = 0; j < 2; j++)
            wmma::store_matrix_sync(
                &sOut[(wn * 32 + j * 16) * SOUT_LD + wm * 32 + i * 16],
                c[i][j], SOUT_LD, wmma::mem_col_major);
    __syncthreads();

    {
        int co = tx >> 2, chunk = tx & 3;
        float bias = bs[co];
        float* o = g_h2 + (size_t)n * C2 * PIX2 + (size_t)co * PIX2 + oy0 * H2;
        const float* src = &sOut[co * SOUT_LD + chunk * 32];
#pragma unroll
        for (int j4 = 0; j4 < 8; j4++) {
            int px = chunk * 32 + j4 * 4;
            if (px >= 120) break;
            float4 y;
            y.x = fmaxf(src[j4 * 4 + 0] + bias, 0.f);
            y.y = fmaxf(src[j4 * 4 + 1] + bias, 0.f);
            y.z = fmaxf(src[j4 * 4 + 2] + bias, 0.f);
            y.w = fmaxf(src[j4 * 4 + 3] + bias, 0.f);
            *(float4*)&o[px] = y;
        }
    }
}

// ---------------------------------------------------------------------------
// Conv3: WMMA tf32 GEMM + BN + ReLU + fused GAP partials (exact R14 form).
// ---------------------------------------------------------------------------
__global__ __launch_bounds__(512, 2) void conv3_gap_kernel(
        const float* __restrict__ b2v) {
    extern __shared__ float s3[];
    float* sW   = s3;
    float* sH   = s3 + 8704;
    float* sOut = s3 + 8704;
    __shared__ float sB2[C3];
    __shared__ float sRed[512];

    int chunk = blockIdx.x, n = blockIdx.y;
    int tx = threadIdx.x;
    int wid = tx >> 5;
    int P0 = chunk * P3;

    if (tx < C3) sB2[tx] = b2v[tx];

    for (int i = tx; i < 128 * 16; i += 512) {
        int row = i >> 4, c4 = i & 15;
        *(float4*)&sW[row * SW_LD + c4 * 4] =
            *(const float4*)&g_w2a[row * C2 + c4 * 4];
    }

    const float* h2n = g_h2 + (size_t)n * C2 * PIX2;
    if (P0 + P3 <= PIX2) {
        for (int i = tx; i < 2048; i += 512) {
            int k = i >> 5, p4 = i & 31;
            float4 v = *(const float4*)&h2n[(size_t)k * PIX2 + P0 + p4 * 4];
            float4 t;
            t.x = f2tf(v.x); t.y = f2tf(v.y); t.z = f2tf(v.z); t.w = f2tf(v.w);
            *(float4*)&sH[k * SH_LD + p4 * 4] = t;
        }
    } else {
        for (int i = tx; i < 2048; i += 512) {
            int k = i >> 5, p4 = i & 31;
            int px = P0 + p4 * 4;
            float4 t = make_float4(0.f, 0.f, 0.f, 0.f);
            if (px + 3 < PIX2) {
                float4 v = *(const float4*)&h2n[(size_t)k * PIX2 + px];
                t.x = f2tf(v.x); t.y = f2tf(v.y); t.z = f2tf(v.z); t.w = f2tf(v.w);
            } else {
#pragma unroll
                for (int e = 0; e < 4; e++)
                    if (px + e < PIX2)
                        ((float*)&t)[e] = f2tf(h2n[(size_t)k * PIX2 + px + e]);
            }
            *(float4*)&sH[k * SH_LD + p4 * 4] = t;
        }
    }
    __syncthreads();

    int wm = wid >> 2, wn = wid & 3;

    wmma::fragment<wmma::accumulator, 16, 16, 8, float> c[2][2];
#pragma unroll
    for (int i = 0; i < 2; i++)
#pragma unroll
        for (int j = 0; j < 2; j++) wmma::fill_fragment(c[i][j], 0.f);

#pragma unroll
    for (int s = 0; s < 8; s++) {
        wmma::fragment<wmma::matrix_a, 16, 16, 8, wmma::precision::tf32,
                       wmma::row_major> a[2];
        wmma::fragment<wmma::matrix_b, 16, 16, 8, wmma::precision::tf32,
                       wmma::row_major> b[2];
#pragma unroll
        for (int i = 0; i < 2; i++)
            wmma::load_matrix_sync(a[i],
                &sW[(wm * 32 + i * 16) * SW_LD + s * 8], SW_LD);
#pragma unroll
        for (int j = 0; j < 2; j++)
            wmma::load_matrix_sync(b[j],
                &sH[(s * 8) * SH_LD + wn * 32 + j * 16], SH_LD);
#pragma unroll
        for (int i = 0; i < 2; i++)
#pragma unroll
            for (int j = 0; j < 2; j++)
                wmma::mma_sync(c[i][j], a[i], b[j], c[i][j]);
    }
    __syncthreads();

    float acc = 0.f;
    int co = tx & 127, seg = tx >> 7;
    float b2c = sB2[co];
#pragma unroll
    for (int h = 0; h < 2; h++) {
        if ((wn >> 1) == h) {
#pragma unroll
            for (int i = 0; i < 2; i++)
#pragma unroll
                for (int j = 0; j < 2; j++)
                    wmma::store_matrix_sync(
                        &sOut[(wm * 32 + i * 16) * S3_OUT_LD
                              + (wn & 1) * 32 + j * 16],
                        c[i][j], S3_OUT_LD, wmma::mem_row_major);
        }
        __syncthreads();
        const float* src = &sOut[co * S3_OUT_LD + seg * 16];
        int pxg0 = P0 + h * 64 + seg * 16;
        if (pxg0 + 16 <= PIX2) {
#pragma unroll
            for (int q = 0; q < 4; q++) {
                float4 v = *(const float4*)&src[q * 4];
                acc += fmaxf(v.x + b2c, 0.f) + fmaxf(v.y + b2c, 0.f)
                     + fmaxf(v.z + b2c, 0.f) + fmaxf(v.w + b2c, 0.f);
            }
        } else {
            for (int q = 0; q < 16; q++)
                if (pxg0 + q < PIX2) acc += fmaxf(src[q] + b2c, 0.f);
        }
        __syncthreads();
    }
    sRed[tx] = acc;
    __syncthreads();
    if (tx < 128)
        g_part[((size_t)n * NCHUNK + chunk) * C3 + tx] =
            sRed[tx] + sRed[tx + 128] + sRed[tx + 256] + sRed[tx + 384];
}

// ---------------------------------------------------------------------------
// Head GEMV with fused GAP reduce
// ---------------------------------------------------------------------------
__global__ void head_kernel(const float* __restrict__ wh,
                            const float* __restrict__ ah,
                            const float* __restrict__ bh,
                            float* __restrict__ out) {
    __shared__ float gs[C3];
    int n = blockIdx.y;
    if (threadIdx.x < C3) {
        int c = threadIdx.x;
        float s = 0.f;
#pragma unroll 4
        for (int ch = 0; ch < NCHUNK; ch++)
            s += g_part[((size_t)n * NCHUNK + ch) * C3 + c];
        gs[c] = s * (1.f / (float)PIX2);
    }
    __syncthreads();

    int o = blockIdx.x * blockDim.x + threadIdx.x;
    if (o >= HEADN) return;

    const float* wr = wh + (size_t)o * C3;
    float dot = 0.f;
#pragma unroll 8
    for (int k = 0; k < C3; k++) dot += __ldg(&wr[k]) * gs[k];
    out[(size_t)n * HEADN + o] = fmaxf(dot * __ldg(&ah[o]) + __ldg(&bh[o]), 0.f);
}

// ---------------------------------------------------------------------------
// Launch
// ---------------------------------------------------------------------------
extern "C" void kernel_launch(void* const* d_in, const int* in_sizes, int n_in,
                              void* d_out, int out_size) {
    const float* x      = (const float*)d_in[0];
    const float* w_stem = (const float*)d_in[1];
    const float* a_stem = (const float*)d_in[2];
    const float* b_stem = (const float*)d_in[3];
    const float* w1     = (const float*)d_in[4];
    const float* a1     = (const float*)d_in[5];
    const float* b1     = (const float*)d_in[6];
    const float* w2     = (const float*)d_in[7];
    const float* a2     = (const float*)d_in[8];
    const float* b2     = (const float*)d_in[9];
    const float* w_head = (const float*)d_in[10];
    const float* a_head = (const float*)d_in[11];
    const float* b_head = (const float*)d_in[12];
    float* out = (float*)d_out;

    cudaFuncSetAttribute(conv2_mma_kernel,
                         cudaFuncAttributeMaxDynamicSharedMemorySize, S2_TOTAL);
    cudaFuncSetAttribute(conv3_gap_kernel,
                         cudaFuncAttributeMaxDynamicSharedMemorySize, S3_TOTAL);

    prep_kernel<<<(C2 * 288 + 255) / 256, 256>>>(w_stem, a_stem, w1, a1, w2, a2);

    conv1_mma_kernel<<<dim3(H1, BN), 256>>>(x, b_stem);

    conv2_mma_kernel<<<dim3(H2 / 2, BN), 256, S2_TOTAL>>>(b1);

    conv3_gap_kernel<<<dim3(NCHUNK, BN), 512, S3_TOTAL>>>(b2);

    head_kernel<<<dim3((HEADN + 255) / 256, BN), 256>>>(w_head, a_head, b_head, out);
}

// round 17
// speedup vs baseline: 1.1187x; 1.1187x over previous
#include <cuda_runtime.h>
#include <cstdint>
#include <mma.h>

using namespace nvcuda;

// ---------------------------------------------------------------------------
// Shapes
// ---------------------------------------------------------------------------
namespace {
constexpr int BN   = 64;
constexpr int HWIN = 240;
constexpr int H1   = 120;
constexpr int H2   = 60;
constexpr int C0   = 3;
constexpr int C1   = 32;
constexpr int C2   = 64;
constexpr int C3   = 128;
constexpr int HEADN = 1280;
constexpr int PIX2  = H2 * H2;                 // 3600
constexpr int NTAP = 9;

// conv2 SMEM plan (floats) — double-buffered A + per-tap B slices
constexpr int SA_LD   = 36;
constexpr int SB_LD   = 68;
constexpr int SA_SZ   = 128 * SA_LD;           // 4608
constexpr int SB_SZ   = 32 * SB_LD;            // 2176
constexpr int S2_A0   = 0;
constexpr int S2_A1   = SA_SZ;
constexpr int S2_B0   = 2 * SA_SZ;
constexpr int S2_B1   = 2 * SA_SZ + SB_SZ;
constexpr int S2_FLTS = 2 * SA_SZ + 2 * SB_SZ; // 13568 floats
constexpr int SOUT_LD = 132;
constexpr int S2_TOTAL = S2_FLTS * 4;          // 54272 B

// conv3 geometry
constexpr int P3     = 128;
constexpr int NCHUNK = (PIX2 + P3 - 1) / P3;   // 29
constexpr int SW_LD  = 68;
constexpr int SH_LD  = 132;
constexpr int S3_OUT_LD = 68;
constexpr int S3_TOTAL  = (8704 + 8704) * 4;   // 69632 B
}

// ---------------------------------------------------------------------------
// Scratch
// ---------------------------------------------------------------------------
__device__ float g_h1[(size_t)BN * H1 * H1 * C1];   // channels-last
__device__ float g_h2[(size_t)BN * C2 * PIX2];      // channel-major
__device__ float g_part[BN * NCHUNK * C3];
__device__ float g_wst[27 * C1];                    // stem [ci*9+tap][co]
__device__ float g_w2b[288 * C2];                   // conv2 B [tap*32+ci][co], tf32
__device__ float g_w2a[C3 * C2];                    // conv3 A [co3][k], tf32, a2-folded

__device__ __forceinline__ float f2tf(float x) {
    uint32_t r;
    asm("cvt.rna.tf32.f32 %0, %1;" : "=r"(r) : "f"(x));
    return __uint_as_float(r);
}
__device__ __forceinline__ uint32_t smem_u32(const void* p) {
    uint32_t a;
    asm("{ .reg .u64 t; cvta.to.shared.u64 t, %1; cvt.u32.u64 %0, t; }"
        : "=r"(a) : "l"(p));
    return a;
}
#define CP_ASYNC16(dst, src, bytes)                                        \
    asm volatile("cp.async.cg.shared.global [%0], [%1], 16, %2;"           \
                 :: "r"(dst), "l"(src), "r"(bytes))
#define CP_COMMIT() asm volatile("cp.async.commit_group;" ::: "memory")
#define CP_WAIT0()  asm volatile("cp.async.wait_group 0;" ::: "memory")

// ---------------------------------------------------------------------------
// Prep
// ---------------------------------------------------------------------------
__global__ void prep_kernel(const float* __restrict__ wstem,
                            const float* __restrict__ w1,
                            const float* __restrict__ a1,
                            const float* __restrict__ w2,
                            const float* __restrict__ a2) {
    int i = blockIdx.x * blockDim.x + threadIdx.x;
    if (i < 27 * C1) {
        int co = i / 27, kk = i % 27;
        g_wst[kk * C1 + co] = wstem[i];
    }
    if (i < C3 * C2) {
        g_w2a[i] = f2tf(w2[i] * a2[i >> 6]);
    }
    if (i < C2 * 288) {
        int co = i / 288, r = i % 288;
        int ci = r / 9, tap = r % 9;
        g_w2b[(tap * 32 + ci) * C2 + co] = f2tf(w1[i] * a1[co]);
    }
}

// ---------------------------------------------------------------------------
// Conv1 (stem): fp32 scalar, channels-last output (exact R14 form)
// ---------------------------------------------------------------------------
__global__ __launch_bounds__(128) void conv1_kernel(
        const float* __restrict__ x,
        const float* __restrict__ a,
        const float* __restrict__ b) {
    __shared__ float sO[9][132];
    __shared__ float sE[9][132];
    __shared__ float ws[27 * C1];
    __shared__ float as[C1], bs[C1];

    int oy = blockIdx.x, n = blockIdx.y;
    int tx = threadIdx.x;

    for (int i = tx; i < 27 * C1; i += 128) ws[i] = g_wst[i];
    if (tx < C1) { as[tx] = a[tx]; bs[tx] = b[tx]; }

    const float* xn = x + (size_t)n * C0 * HWIN * HWIN;
#pragma unroll
    for (int r = 0; r < 9; r++) {
        const int ky = r / 3, ci = r % 3;
        int iy = oy * 2 - 1 + ky;
        const float* row = xn + ci * HWIN * HWIN + iy * HWIN;
        bool rowok = (iy >= 0);
        for (int j = tx; j < 264; j += 128) {
            if (j < 132) {
                int sx = 2 * j - 1;
                sO[r][j] = (rowok && j <= 120 && sx >= 0) ? row[sx] : 0.f;
            } else {
                int jj = j - 132;
                sE[r][jj] = (rowok && jj <= 119) ? row[2 * jj] : 0.f;
            }
        }
    }
    __syncthreads();

    int cg = tx & 3, pg = tx >> 2;
    int c0 = cg * 8, ox0 = pg * 4;

    float acc[8][4];
#pragma unroll
    for (int i = 0; i < 8; i++)
#pragma unroll
        for (int j = 0; j < 4; j++) acc[i][j] = 0.f;

#pragma unroll
    for (int ky = 0; ky < 3; ky++) {
#pragma unroll
        for (int ci = 0; ci < 3; ci++) {
            int r = ky * 3 + ci;
            float4 o = *(const float4*)&sO[r][ox0];
            float  o4 = sO[r][ox0 + 4];
            float4 e = *(const float4*)&sE[r][ox0];
#pragma unroll
            for (int kx = 0; kx < 3; kx++) {
                float v0, v1, v2, v3;
                if (kx == 0)      { v0 = o.x; v1 = o.y; v2 = o.z; v3 = o.w; }
                else if (kx == 1) { v0 = e.x; v1 = e.y; v2 = e.z; v3 = e.w; }
                else              { v0 = o.y; v1 = o.z; v2 = o.w; v3 = o4;  }
                const float* wp = &ws[(ci * 9 + ky * 3 + kx) * C1 + c0];
                float4 wa = *(const float4*)wp;
                float4 wb = *(const float4*)(wp + 4);
                float w8[8] = {wa.x, wa.y, wa.z, wa.w, wb.x, wb.y, wb.z, wb.w};
#pragma unroll
                for (int i = 0; i < 8; i++) {
                    acc[i][0] += w8[i] * v0;
                    acc[i][1] += w8[i] * v1;
                    acc[i][2] += w8[i] * v2;
                    acc[i][3] += w8[i] * v3;
                }
            }
        }
    }

    if (pg < 30) {
        float* outp = g_h1 + (((size_t)n * H1 + oy) * H1 + ox0) * C1 + c0;
#pragma unroll
        for (int j = 0; j < 4; j++) {
            float4 lo, hi;
            lo.x = fmaxf(acc[0][j] * as[c0 + 0] + bs[c0 + 0], 0.f);
            lo.y = fmaxf(acc[1][j] * as[c0 + 1] + bs[c0 + 1], 0.f);
            lo.z = fmaxf(acc[2][j] * as[c0 + 2] + bs[c0 + 2], 0.f);
            lo.w = fmaxf(acc[3][j] * as[c0 + 3] + bs[c0 + 3], 0.f);
            hi.x = fmaxf(acc[4][j] * as[c0 + 4] + bs[c0 + 4], 0.f);
            hi.y = fmaxf(acc[5][j] * as[c0 + 5] + bs[c0 + 5], 0.f);
            hi.z = fmaxf(acc[6][j] * as[c0 + 6] + bs[c0 + 6], 0.f);
            hi.w = fmaxf(acc[7][j] * as[c0 + 7] + bs[c0 + 7], 0.f);
            *(float4*)&outp[j * C1]     = lo;
            *(float4*)&outp[j * C1 + 4] = hi;
        }
    }
}

// ---------------------------------------------------------------------------
// Conv2: WMMA tf32 implicit GEMM, double-buffered, cp.async staging.
// A fed as raw fp32 bits (tf32 truncation); B pre-rounded in prep.
// ---------------------------------------------------------------------------
__global__ __launch_bounds__(256) void conv2_mma_kernel(
        const float* __restrict__ b1) {
    extern __shared__ float smf[];
    __shared__ float bs[C2];

    int tx = threadIdx.x;
    int wid = tx >> 5;
    int oy0 = blockIdx.x * 2;
    int n = blockIdx.y;

    if (tx < C2) bs[tx] = b1[tx];

    uint32_t sA_u[2] = { smem_u32(smf + S2_A0), smem_u32(smf + S2_A1) };
    uint32_t sB_u[2] = { smem_u32(smf + S2_B0), smem_u32(smf + S2_B1) };
    float*   sA_f[2] = { smf + S2_A0, smf + S2_A1 };
    float*   sB_f[2] = { smf + S2_B0, smf + S2_B1 };

    int wm = wid & 3;
    int wn = wid >> 2;

    wmma::fragment<wmma::accumulator, 16, 16, 8, float> c[2][2];
#pragma unroll
    for (int i = 0; i < 2; i++)
#pragma unroll
        for (int j = 0; j < 2; j++) wmma::fill_fragment(c[i][j], 0.f);

    const float* h1n = g_h1 + (size_t)n * H1 * H1 * C1;

    // per-thread A items (item = tx + it*256; 1024 16B chunks)
    int ipx[4], ic4[4], ioy[4], iox[4];
    bool ival[4];
    uint32_t aoff[4];
#pragma unroll
    for (int it = 0; it < 4; it++) {
        int i = tx + it * 256;
        ipx[it] = i >> 3;
        ic4[it] = i & 7;
        ival[it] = (ipx[it] < 120);
        ioy[it] = oy0 + (ipx[it] >= 60 ? 1 : 0);
        iox[it] = ipx[it] >= 60 ? ipx[it] - 60 : ipx[it];
        aoff[it] = (uint32_t)(ipx[it] * SA_LD + ic4[it] * 4) * 4u;
    }
    // per-thread B items (512 16B chunks -> 2 per thread)
    int brow[2], bc4[2];
    uint32_t boff[2];
#pragma unroll
    for (int it = 0; it < 2; it++) {
        int i = tx + it * 256;
        brow[it] = i >> 4;
        bc4[it]  = i & 15;
        boff[it] = (uint32_t)(brow[it] * SB_LD + bc4[it] * 4) * 4u;
    }

    auto issue_tap = [&](int tap, int buf) {
        int ky = tap / 3, kx = tap % 3;
#pragma unroll
        for (int it = 0; it < 4; it++) {
            int iy = ioy[it] * 2 - 1 + ky;
            int ix = iox[it] * 2 - 1 + kx;
            bool ok = ival[it] && (unsigned)iy < (unsigned)H1
                               && (unsigned)ix < (unsigned)H1;
            const float* src = &h1n[((size_t)iy * H1 + ix) * C1 + ic4[it] * 4];
            CP_ASYNC16(sA_u[buf] + aoff[it], src, ok ? 16 : 0);
        }
#pragma unroll
        for (int it = 0; it < 2; it++) {
            const float* src = &g_w2b[(tap * 32 + brow[it]) * C2 + bc4[it] * 4];
            CP_ASYNC16(sB_u[buf] + boff[it], src, 16);
        }
        CP_COMMIT();
    };

    // prologue: tap 0 into buffer 0
    issue_tap(0, 0);
    CP_WAIT0();
    __syncthreads();

    for (int tap = 0; tap < NTAP; tap++) {
        int cur = tap & 1, nxt = cur ^ 1;

        if (tap < NTAP - 1) issue_tap(tap + 1, nxt);   // overlaps MMA below

        float* sA = sA_f[cur];
        float* sB = sB_f[cur];
#pragma unroll
        for (int s = 0; s < 4; s++) {
            wmma::fragment<wmma::matrix_a, 16, 16, 8, wmma::precision::tf32,
                           wmma::row_major> a[2];
            wmma::fragment<wmma::matrix_b, 16, 16, 8, wmma::precision::tf32,
                           wmma::row_major> b[2];
#pragma unroll
            for (int i = 0; i < 2; i++)
                wmma::load_matrix_sync(a[i],
                    &sA[(wm * 32 + i * 16) * SA_LD + s * 8], SA_LD);
#pragma unroll
            for (int j = 0; j < 2; j++)
                wmma::load_matrix_sync(b[j],
                    &sB[(s * 8) * SB_LD + wn * 32 + j * 16], SB_LD);
#pragma unroll
            for (int i = 0; i < 2; i++)
#pragma unroll
                for (int j = 0; j < 2; j++)
                    wmma::mma_sync(c[i][j], a[i], b[j], c[i][j]);
        }

        if (tap < NTAP - 1) CP_WAIT0();
        __syncthreads();
    }

    // epilogue: col-major stage -> bias+ReLU -> channel-major g_h2
    float* sOut = smf;
#pragma unroll
    for (int i = 0; i < 2; i++)
#pragma unroll
        for (int j = 0; j < 2; j++)
            wmma::store_matrix_sync(
                &sOut[(wn * 32 + j * 16) * SOUT_LD + wm * 32 + i * 16],
                c[i][j], SOUT_LD, wmma::mem_col_major);
    __syncthreads();

    {
        int co = tx >> 2, chunk = tx & 3;
        float bias = bs[co];
        float* o = g_h2 + (size_t)n * C2 * PIX2 + (size_t)co * PIX2 + oy0 * H2;
        const float* src = &sOut[co * SOUT_LD + chunk * 32];
#pragma unroll
        for (int j4 = 0; j4 < 8; j4++) {
            int px = chunk * 32 + j4 * 4;
            if (px >= 120) break;
            float4 y;
            y.x = fmaxf(src[j4 * 4 + 0] + bias, 0.f);
            y.y = fmaxf(src[j4 * 4 + 1] + bias, 0.f);
            y.z = fmaxf(src[j4 * 4 + 2] + bias, 0.f);
            y.w = fmaxf(src[j4 * 4 + 3] + bias, 0.f);
            *(float4*)&o[px] = y;
        }
    }
}

// ---------------------------------------------------------------------------
// Conv3: WMMA tf32 GEMM + BN + ReLU + fused GAP partials.
// cp.async staging (sW copy, sH raw-bit tf32); rest exact R14 form.
// ---------------------------------------------------------------------------
__global__ __launch_bounds__(512, 2) void conv3_gap_kernel(
        const float* __restrict__ b2v) {
    extern __shared__ float s3[];
    float* sW   = s3;            // [128][SW_LD=68]
    float* sH   = s3 + 8704;     // [64][SH_LD=132]
    float* sOut = s3 + 8704;     // [128][68] overlay after MMA
    __shared__ float sB2[C3];
    __shared__ float sRed[512];

    int chunk = blockIdx.x, n = blockIdx.y;
    int tx = threadIdx.x;
    int wid = tx >> 5;
    int P0 = chunk * P3;

    if (tx < C3) sB2[tx] = b2v[tx];

    uint32_t sW_u = smem_u32(sW);
    uint32_t sH_u = smem_u32(sH);

    // stage W2 via cp.async (pre-rounded tf32): 2048 chunks, 4/thread
    for (int i = tx; i < 128 * 16; i += 512) {
        int row = i >> 4, c4 = i & 15;
        CP_ASYNC16(sW_u + (uint32_t)(row * SW_LD + c4 * 4) * 4u,
                   &g_w2a[row * C2 + c4 * 4], 16);
    }
    // stage H tile via cp.async (raw fp32 bits as tf32): 2048 chunks
    const float* h2n = g_h2 + (size_t)n * C2 * PIX2;
    for (int i = tx; i < 2048; i += 512) {
        int k = i >> 5, p4 = i & 31;
        int px = P0 + p4 * 4;
        // PIX2 % 16 == 0 and P0 % 128 == 0 -> chunk fully valid or invalid
        CP_ASYNC16(sH_u + (uint32_t)(k * SH_LD + p4 * 4) * 4u,
                   &h2n[(size_t)k * PIX2 + px],
                   (px + 4 <= PIX2) ? 16 : 0);
    }
    CP_COMMIT();
    CP_WAIT0();
    __syncthreads();

    int wm = wid >> 2, wn = wid & 3;     // 4 co-groups x 4 px-groups

    wmma::fragment<wmma::accumulator, 16, 16, 8, float> c[2][2];
#pragma unroll
    for (int i = 0; i < 2; i++)
#pragma unroll
        for (int j = 0; j < 2; j++) wmma::fill_fragment(c[i][j], 0.f);

#pragma unroll
    for (int s = 0; s < 8; s++) {
        wmma::fragment<wmma::matrix_a, 16, 16, 8, wmma::precision::tf32,
                       wmma::row_major> a[2];
        wmma::fragment<wmma::matrix_b, 16, 16, 8, wmma::precision::tf32,
                       wmma::row_major> b[2];
#pragma unroll
        for (int i = 0; i < 2; i++)
            wmma::load_matrix_sync(a[i],
                &sW[(wm * 32 + i * 16) * SW_LD + s * 8], SW_LD);
#pragma unroll
        for (int j = 0; j < 2; j++)
            wmma::load_matrix_sync(b[j],
                &sH[(s * 8) * SH_LD + wn * 32 + j * 16], SH_LD);
#pragma unroll
        for (int i = 0; i < 2; i++)
#pragma unroll
            for (int j = 0; j < 2; j++)
                wmma::mma_sync(c[i][j], a[i], b[j], c[i][j]);
    }
    __syncthreads();

    float acc = 0.f;
    int co = tx & 127, seg = tx >> 7;    // 128 co x 4 segments of 16 px
    float b2c = sB2[co];
#pragma unroll
    for (int h = 0; h < 2; h++) {
        if ((wn >> 1) == h) {
#pragma unroll
            for (int i = 0; i < 2; i++)
#pragma unroll
                for (int j = 0; j < 2; j++)
                    wmma::store_matrix_sync(
                        &sOut[(wm * 32 + i * 16) * S3_OUT_LD
                              + (wn & 1) * 32 + j * 16],
                        c[i][j], S3_OUT_LD, wmma::mem_row_major);
        }
        __syncthreads();
        const float* src = &sOut[co * S3_OUT_LD + seg * 16];
        int pxg0 = P0 + h * 64 + seg * 16;
        if (pxg0 + 16 <= PIX2) {
#pragma unroll
            for (int q = 0; q < 4; q++) {
                float4 v = *(const float4*)&src[q * 4];
                acc += fmaxf(v.x + b2c, 0.f) + fmaxf(v.y + b2c, 0.f)
                     + fmaxf(v.z + b2c, 0.f) + fmaxf(v.w + b2c, 0.f);
            }
        } else {
            for (int q = 0; q < 16; q++)
                if (pxg0 + q < PIX2) acc += fmaxf(src[q] + b2c, 0.f);
        }
        __syncthreads();
    }
    sRed[tx] = acc;
    __syncthreads();
    if (tx < 128)
        g_part[((size_t)n * NCHUNK + chunk) * C3 + tx] =
            sRed[tx] + sRed[tx + 128] + sRed[tx + 256] + sRed[tx + 384];
}

// ---------------------------------------------------------------------------
// Head GEMV with fused GAP reduce
// ---------------------------------------------------------------------------
__global__ void head_kernel(const float* __restrict__ wh,
                            const float* __restrict__ ah,
                            const float* __restrict__ bh,
                            float* __restrict__ out) {
    __shared__ float gs[C3];
    int n = blockIdx.y;
    if (threadIdx.x < C3) {
        int c = threadIdx.x;
        float s = 0.f;
#pragma unroll 4
        for (int ch = 0; ch < NCHUNK; ch++)
            s += g_part[((size_t)n * NCHUNK + ch) * C3 + c];
        gs[c] = s * (1.f / (float)PIX2);
    }
    __syncthreads();

    int o = blockIdx.x * blockDim.x + threadIdx.x;
    if (o >= HEADN) return;

    const float* wr = wh + (size_t)o * C3;
    float dot = 0.f;
#pragma unroll 8
    for (int k = 0; k < C3; k++) dot += __ldg(&wr[k]) * gs[k];
    out[(size_t)n * HEADN + o] = fmaxf(dot * __ldg(&ah[o]) + __ldg(&bh[o]), 0.f);
}

// ---------------------------------------------------------------------------
// Launch
// ---------------------------------------------------------------------------
extern "C" void kernel_launch(void* const* d_in, const int* in_sizes, int n_in,
                              void* d_out, int out_size) {
    const float* x      = (const float*)d_in[0];
    const float* w_stem = (const float*)d_in[1];
    const float* a_stem = (const float*)d_in[2];
    const float* b_stem = (const float*)d_in[3];
    const float* w1     = (const float*)d_in[4];
    const float* a1     = (const float*)d_in[5];
    const float* b1     = (const float*)d_in[6];
    const float* w2     = (const float*)d_in[7];
    const float* a2     = (const float*)d_in[8];
    const float* b2     = (const float*)d_in[9];
    const float* w_head = (const float*)d_in[10];
    const float* a_head = (const float*)d_in[11];
    const float* b_head = (const float*)d_in[12];
    float* out = (float*)d_out;

    cudaFuncSetAttribute(conv2_mma_kernel,
                         cudaFuncAttributeMaxDynamicSharedMemorySize, S2_TOTAL);
    cudaFuncSetAttribute(conv3_gap_kernel,
                         cudaFuncAttributeMaxDynamicSharedMemorySize, S3_TOTAL);

    prep_kernel<<<(C2 * 288 + 255) / 256, 256>>>(w_stem, w1, a1, w2, a2);

    conv1_kernel<<<dim3(H1, BN), 128>>>(x, a_stem, b_stem);

    conv2_mma_kernel<<<dim3(H2 / 2, BN), 256, S2_TOTAL>>>(b1);

    conv3_gap_kernel<<<dim3(NCHUNK, BN), 512, S3_TOTAL>>>(b2);

    head_kernel<<<dim3((HEADN + 255) / 256, BN), 256>>>(w_head, a_head, b_head, out);
}